// round 6
// baseline (speedup 1.0000x reference)
#include <cuda_runtime.h>
#include <math.h>
#include <stdint.h>

#define BATCH 128
#define HID   512
#define ATT   128
#define TT    256
#define CC    256
#define NEG_SLOPE 0.01f
#define NBLK  128
#define NTHR  512

// -------------------- device-global scratch (no allocs allowed) ----------------
__device__ float g_h1[BATCH * HID];
__device__ float g_c1[BATCH * HID];
__device__ float g_h2[BATCH * HID];
__device__ float g_c2[BATCH * HID];
__device__ float g_h3[BATCH * HID];
__device__ float g_c3[BATCH * HID];
__device__ float g_ctx[BATCH * ATT];
__device__ float g_part[8 * BATCH * 2048];   // split-K partials, gate GEMMs
__device__ float g_mpart[8 * BATCH * HID];   // split-K partials, mlp GEMM
__device__ unsigned g_flags[NBLK];           // grid barrier epochs (monotonic)

// -------------------- shared memory ----------------------------------------------
struct GemmSmem { float ahi[4096]; float alo[4096]; float whi[4096]; float wlo[4096]; };
struct AttSmem  { float hs[NTHR]; float pr[NTHR]; float qs[ATT]; float at[TT]; float red[16]; };
struct ProjSmem { float ms[HID]; float pr[NTHR]; float red[16]; };
union SmemAll { GemmSmem g; AttSmem a; ProjSmem p; };
#define SMEM_BYTES (sizeof(SmemAll) + 1024)

// -------------------- tf32 helpers -------------------------------------------------
__device__ __forceinline__ float tf32_rna(float x) {
    uint32_t r; asm("cvt.rna.tf32.f32 %0, %1;" : "=r"(r) : "f"(x));
    return __uint_as_float(r);
}

// m16n8k8 tf32 mma: D += A x B   (A row-major 16x8, B col-major 8x8)
__device__ __forceinline__ void mma8(float* d, const uint32_t* a, const uint32_t* b) {
    asm volatile(
        "mma.sync.aligned.m16n8k8.row.col.f32.tf32.tf32.f32 "
        "{%0,%1,%2,%3}, {%4,%5,%6,%7}, {%8,%9}, {%0,%1,%2,%3};"
        : "+f"(d[0]), "+f"(d[1]), "+f"(d[2]), "+f"(d[3])
        : "r"(a[0]), "r"(a[1]), "r"(a[2]), "r"(a[3]), "r"(b[0]), "r"(b[1]));
}

// smem layout: addr(m,k) = m*32 + ((k + 4*(m&7) + ((m>>3)&3)) & 31)
// conflict-free for BOTH 32-consecutive-row scalar stores AND 8row x 4col frag loads.
__device__ __forceinline__ int swz(int m, int k) {
    return (m << 5) + ((k + ((m & 7) << 2) + ((m >> 3) & 3)) & 31);
}

// -------------------- grid barrier -------------------------------------------------
__device__ __forceinline__ void st_rel(unsigned* p, unsigned v) {
    asm volatile("st.release.gpu.u32 [%0], %1;" :: "l"(p), "r"(v) : "memory");
}
__device__ __forceinline__ unsigned ld_acq(const unsigned* p) {
    unsigned v;
    asm volatile("ld.acquire.gpu.u32 %0, [%1];" : "=r"(v) : "l"(p) : "memory");
    return v;
}
__device__ __forceinline__ void gbar(unsigned target) {
    __syncthreads();
    if (threadIdx.x == 0) st_rel(&g_flags[blockIdx.x], target);
    if (threadIdx.x < NBLK) {
        while (ld_acq(&g_flags[threadIdx.x]) < target) __nanosleep(32);
    }
    __syncthreads();
}

// -------------------- reductions (512 threads = 16 warps) ---------------------------
__device__ __forceinline__ float warpMax(float v) {
    #pragma unroll
    for (int o = 16; o; o >>= 1) v = fmaxf(v, __shfl_xor_sync(0xffffffffu, v, o));
    return v;
}
__device__ __forceinline__ float warpSum(float v) {
    #pragma unroll
    for (int o = 16; o; o >>= 1) v += __shfl_xor_sync(0xffffffffu, v, o);
    return v;
}
__device__ float blockMax(float v, float* red) {
    v = warpMax(v);
    if ((threadIdx.x & 31) == 0) red[threadIdx.x >> 5] = v;
    __syncthreads();
    if (threadIdx.x < 32) {
        float x = (threadIdx.x < 16) ? red[threadIdx.x] : -3.4e38f;
        x = warpMax(x);
        if (threadIdx.x == 0) red[0] = x;
    }
    __syncthreads();
    float r = red[0];
    __syncthreads();
    return r;
}
__device__ float blockSum(float v, float* red) {
    v = warpSum(v);
    if ((threadIdx.x & 31) == 0) red[threadIdx.x >> 5] = v;
    __syncthreads();
    if (threadIdx.x < 32) {
        float x = (threadIdx.x < 16) ? red[threadIdx.x] : 0.f;
        x = warpSum(x);
        if (threadIdx.x == 0) red[0] = x;
    }
    __syncthreads();
    float r = red[0];
    __syncthreads();
    return r;
}

// -------------------- GEMM raw loader (GMEM -> regs) --------------------------------
__device__ __forceinline__ void load_raw(
    float4* a, float4* w, int kb, int N0, int lm, int lkg, int t,
    const float* emb, const int* Yin, int ystride, int s0,
    const float* p1, int l1, int s1,
    const float* p2, int l2,
    const float* W1, int wk1, const float* W2)
{
    #pragma unroll
    for (int i = 0; i < 2; i++) {
        const int gk = kb + lkg + i * 4;
        const float* ap;
        if (gk < s0)      ap = emb + (size_t)Yin[lm * ystride + t] * HID + gk;
        else if (gk < s1) ap = p1 + (size_t)lm * l1 + (gk - s0);
        else              ap = p2 + (size_t)lm * l2 + (gk - s1);
        a[i] = *reinterpret_cast<const float4*>(ap);
        const float* wp = (gk < wk1)
            ? W1 + (size_t)(N0 + lm) * wk1 + gk
            : W2 + (size_t)(N0 + lm) * HID + (gk - wk1);
        w[i] = *reinterpret_cast<const float4*>(wp);
    }
}

// stage 8 raw floats as tf32 hi/lo into swizzled smem (row lm, cols lkg..lkg+7)
__device__ __forceinline__ void stage8(float* hi, float* lo, int lm, int lkg,
                                       float4 v0, float4 v1)
{
    const float v[8] = {v0.x, v0.y, v0.z, v0.w, v1.x, v1.y, v1.z, v1.w};
    const int S = ((lm & 7) << 2) + ((lm >> 3) & 3);
    const int base = lm << 5;
    #pragma unroll
    for (int i = 0; i < 8; i++) {
        const int col = (lkg + i + S) & 31;
        const float h = tf32_rna(v[i]);
        hi[base + col] = h;
        lo[base + col] = tf32_rna(v[i] - h);
    }
}

// -------------------- tensor-core GEMM phase (3xTF32 via mma.sync) ------------------
// part[ks][BATCH][partN] = A(128 x Kslice) @ W(128 x Kslice)^T  per (n-tile, ks) job.
// A virtual row m: k<s0: emb[Yin[m*ystride+t]] ; k<s1: p1 (ld l1) ; else p2 (ld l2).
// W virtual row n: k<wk1: W1 (ld wk1) ; else W2 (ld HID).
__device__ void gemm_mma(SmemAll& SS, int t,
    float* part, int partN, int ntN, int n32, int ksplit,
    const float* emb, const int* Yin, int ystride, int s0,
    const float* p1, int l1, int s1,
    const float* p2, int l2,
    const float* W1, int wk1, const float* W2)
{
    const int bid = blockIdx.x;
    if (bid >= ntN * ksplit) return;
    float* Ahi = SS.g.ahi; float* Alo = SS.g.alo;
    float* Whi = SS.g.whi; float* Wlo = SS.g.wlo;

    const int tid = threadIdx.x;
    const int nt = bid / ksplit, ks = bid % ksplit;
    const int N0 = nt * 128;
    const int q = n32 / ksplit, r = n32 % ksplit;
    const int cnt = q + (ks < r ? 1 : 0);
    const int c0 = ks * q + (ks < r ? ks : r);

    const int lm  = tid & 127;          // staging row (A: m, W: n-local)
    const int lkg = (tid >> 7) << 3;    // staging k offset (8 floats per thread)
    const int lane = tid & 31;
    const int wid = tid >> 5;
    const int wm = wid & 7;             // warp M-tile (16 rows)
    const int wn = wid >> 3;            // warp N-half (64 cols)
    const int fr = lane >> 2;           // fragment row  (0..7)
    const int fc = lane & 3;            // fragment col  (0..3)

    float acc[8][4];
    #pragma unroll
    for (int i = 0; i < 8; i++)
        #pragma unroll
        for (int j = 0; j < 4; j++) acc[i][j] = 0.f;

    float4 ar[2], wr[2];
    load_raw(ar, wr, c0 * 32, N0, lm, lkg, t,
             emb, Yin, ystride, s0, p1, l1, s1, p2, l2, W1, wk1, W2);

    for (int cc = 0; cc < cnt; cc++) {
        __syncthreads();
        stage8(Ahi, Alo, lm, lkg, ar[0], ar[1]);
        stage8(Whi, Wlo, lm, lkg, wr[0], wr[1]);
        __syncthreads();

        if (cc + 1 < cnt) {
            load_raw(ar, wr, (c0 + cc + 1) * 32, N0, lm, lkg, t,
                     emb, Yin, ystride, s0, p1, l1, s1, p2, l2, W1, wk1, W2);
        }

        #pragma unroll
        for (int kk = 0; kk < 4; kk++) {
            const int k0 = kk * 8;
            const int ra = 16 * wm + fr;
            uint32_t ah[4], al[4];
            ah[0] = __float_as_uint(Ahi[swz(ra,     k0 + fc)]);
            ah[1] = __float_as_uint(Ahi[swz(ra + 8, k0 + fc)]);
            ah[2] = __float_as_uint(Ahi[swz(ra,     k0 + fc + 4)]);
            ah[3] = __float_as_uint(Ahi[swz(ra + 8, k0 + fc + 4)]);
            al[0] = __float_as_uint(Alo[swz(ra,     k0 + fc)]);
            al[1] = __float_as_uint(Alo[swz(ra + 8, k0 + fc)]);
            al[2] = __float_as_uint(Alo[swz(ra,     k0 + fc + 4)]);
            al[3] = __float_as_uint(Alo[swz(ra + 8, k0 + fc + 4)]);
            #pragma unroll
            for (int n2 = 0; n2 < 8; n2++) {
                const int nb = 64 * wn + n2 * 8 + fr;
                uint32_t bh[2], bl[2];
                bh[0] = __float_as_uint(Whi[swz(nb, k0 + fc)]);
                bh[1] = __float_as_uint(Whi[swz(nb, k0 + fc + 4)]);
                bl[0] = __float_as_uint(Wlo[swz(nb, k0 + fc)]);
                bl[1] = __float_as_uint(Wlo[swz(nb, k0 + fc + 4)]);
                mma8(acc[n2], ah, bh);
                mma8(acc[n2], ah, bl);
                mma8(acc[n2], al, bh);
            }
        }
    }

    // epilogue: write split-K partials
    #pragma unroll
    for (int n2 = 0; n2 < 8; n2++) {
        const int col = N0 + 64 * wn + n2 * 8 + 2 * fc;
        const int row0 = 16 * wm + fr;
        float* op0 = part + (size_t)(ks * BATCH + row0) * partN + col;
        float* op1 = part + (size_t)(ks * BATCH + row0 + 8) * partN + col;
        *reinterpret_cast<float2*>(op0) = make_float2(acc[n2][0], acc[n2][1]);
        *reinterpret_cast<float2*>(op1) = make_float2(acc[n2][2], acc[n2][3]);
    }
}

// -------------------- LSTM pointwise update (block = batch row) ---------------------
__device__ void update_phase(float* h, float* c, const float* bih, const float* bhh)
{
    const int b = blockIdx.x;
    const int j = threadIdx.x;   // 0..511 == HID
    float gi = bih[j] + bhh[j];
    float gf = bih[j + 512] + bhh[j + 512];
    float gg = bih[j + 1024] + bhh[j + 1024];
    float go = bih[j + 1536] + bhh[j + 1536];
    #pragma unroll
    for (int ks = 0; ks < 8; ks++) {
        const float* pk = g_part + (size_t)(ks * BATCH + b) * 2048;
        gi += pk[j];
        gf += pk[j + 512];
        gg += pk[j + 1024];
        go += pk[j + 1536];
    }
    const float ig = 1.f / (1.f + expf(-gi));
    const float fg = 1.f / (1.f + expf(-gf));
    const float og = 1.f / (1.f + expf(-go));
    const float gv = tanhf(gg);
    const int idx = b * HID + j;
    const float cn = fg * c[idx] + ig * gv;
    c[idx] = cn;
    h[idx] = og * tanhf(cn);
}

// -------------------- fused attention (block = batch row, 512 thr) ------------------
__device__ void attend_phase(SmemAll& SS, const float* key, const float* value,
                             const int* flens, const float* Wq, const float* bq)
{
    AttSmem& A = SS.a;
    const int b = blockIdx.x;
    const int tid = threadIdx.x;

    A.hs[tid] = g_h3[b * HID + tid];
    __syncthreads();

    // q = h3 @ Wq^T + bq : 4 threads per output a, 128 k each
    {
        const int a = tid & 127;
        const int p = tid >> 7;
        const float* wr = Wq + (size_t)a * HID + p * 128;
        const float* hr = A.hs + p * 128;
        float s = 0.f;
        #pragma unroll 8
        for (int k = 0; k < 128; k += 4) {
            const float4 w = *reinterpret_cast<const float4*>(wr + k);
            s += w.x * hr[k] + w.y * hr[k + 1] + w.z * hr[k + 2] + w.w * hr[k + 3];
        }
        A.pr[tid] = s;
    }
    __syncthreads();
    if (tid < ATT)
        A.qs[tid] = A.pr[tid] + A.pr[tid + 128] + A.pr[tid + 256] + A.pr[tid + 384] + bq[tid];
    __syncthreads();

    // energy: 2 threads per position t (64 a each)
    {
        const int tp = tid & 255;
        const int hf = tid >> 8;
        const float* kp = key + (size_t)b * ATT * TT + tp;
        float e = 0.f;
        #pragma unroll 8
        for (int a = 0; a < 64; a++) e += A.qs[hf * 64 + a] * kp[(size_t)(hf * 64 + a) * TT];
        A.pr[tid] = e;
    }
    __syncthreads();

    const int flen = flens[b] >> 3;
    const float ev = (tid < 256) ? (A.pr[tid] + A.pr[tid + 256]) : -3.4e38f;
    const float mx = blockMax(ev, A.red);
    const float w = (tid < 256 && tid < flen) ? expf(ev - mx) : 0.f;
    const float sm = blockSum(w, A.red);
    if (tid < 256) A.at[tid] = w / sm;
    __syncthreads();

    // ctx = attn @ value : 4 threads per output v, 64 t each
    {
        const int v = tid & 127;
        const int p = tid >> 7;
        const float* vp = value + (size_t)b * TT * ATT + (size_t)(p * 64) * ATT + v;
        float cs = 0.f;
        #pragma unroll 8
        for (int t2 = 0; t2 < 64; t2++) cs += A.at[p * 64 + t2] * vp[(size_t)t2 * ATT];
        A.pr[tid] = cs;
    }
    __syncthreads();
    if (tid < ATT)
        g_ctx[b * ATT + tid] = A.pr[tid] + A.pr[tid + 128] + A.pr[tid + 256] + A.pr[tid + 384];
    __syncthreads();
}

// -------------------- mlp-combine + projection + log-softmax ------------------------
__device__ void proj_phase(SmemAll& SS, const float* emb, const float* bproj,
                           const float* bmlp, float* out, int t, int ml)
{
    ProjSmem& P = SS.p;
    const int b = blockIdx.x;
    const int tid = threadIdx.x;

    // combine mlp split-K partials + bias + LeakyReLU (fixed order => deterministic)
    {
        float s = bmlp[tid];
        #pragma unroll
        for (int ks = 0; ks < 8; ks++)
            s += g_mpart[((size_t)(ks * BATCH) + b) * HID + tid];
        P.ms[tid] = (s >= 0.f) ? s : NEG_SLOPE * s;
    }
    __syncthreads();

    // logits: 2 threads per class c (256 k each)
    {
        const int c = tid & 255;
        const int hf = tid >> 8;
        const float* er = emb + (size_t)c * HID + hf * 256;
        const float* mr = P.ms + hf * 256;
        float s = 0.f;
        #pragma unroll 8
        for (int k = 0; k < 256; k += 4) {
            const float4 w = *reinterpret_cast<const float4*>(er + k);
            s += w.x * mr[k] + w.y * mr[k + 1] + w.z * mr[k + 2] + w.w * mr[k + 3];
        }
        P.pr[tid] = s;
    }
    __syncthreads();

    const float lv = (tid < 256) ? (P.pr[tid] + P.pr[tid + 256] + bproj[tid]) : -3.4e38f;
    const float mx = blockMax(lv, P.red);
    const float ex = (tid < 256) ? expf(lv - mx) : 0.f;
    const float sm = blockSum(ex, P.red);
    if (tid < 256)
        out[((size_t)b * ml + t) * CC + tid] = lv - mx - logf(sm);
    __syncthreads();
}

// -------------------- persistent megakernel -----------------------------------------
__global__ __launch_bounds__(NTHR, 1) void mega_kernel(
    const float* key, const float* value, const int* Yin, const int* flens,
    const float* emb, const float* Wq, const float* bq,
    const float* Wih1, const float* Whh1, const float* bih1, const float* bhh1,
    const float* Wih2, const float* Whh2, const float* bih2, const float* bhh2,
    const float* Wih3, const float* Whh3, const float* bih3, const float* bhh3,
    const float* Wmlp, const float* bmlp, const float* bproj,
    const float* h00, const float* h01, const float* h02,
    const float* c00, const float* c01, const float* c02,
    float* out, int ml, int ystride)
{
    extern __shared__ char dyn_smem[];
    char* sb = (char*)((((uintptr_t)dyn_smem) + 1023) & ~(uintptr_t)1023);
    SmemAll& S = *reinterpret_cast<SmemAll*>(sb);

    const int tid = threadIdx.x;
    const unsigned base = g_flags[blockIdx.x];   // monotonic epochs across replays
    unsigned bn = 0;

    // init state (broadcast initial h/c); 128*512 threads == BATCH*HID
    {
        const int idx = blockIdx.x * NTHR + tid;
        const int j = idx & 511;
        g_h1[idx] = h00[j]; g_h2[idx] = h01[j]; g_h3[idx] = h02[j];
        g_c1[idx] = c00[j]; g_c2[idx] = c01[j]; g_c3[idx] = c02[j];
    }
    gbar(base + ++bn);
    attend_phase(S, key, value, flens, Wq, bq);
    gbar(base + ++bn);

    for (int t = 0; t < ml; t++) {
        // LSTM1: A = [emb[y_t] | ctx | h1], W = [Wih1 | Whh1], K=1152
        gemm_mma(S, t, g_part, 2048, 16, 36, 8,
                 emb, Yin, ystride, 512,
                 g_ctx, ATT, 640, g_h1, HID,
                 Wih1, 640, Whh1);
        gbar(base + ++bn);
        update_phase(g_h1, g_c1, bih1, bhh1);
        gbar(base + ++bn);

        // LSTM2: A = [h1 | h2], K=1024
        gemm_mma(S, t, g_part, 2048, 16, 32, 8,
                 nullptr, nullptr, 0, 0,
                 g_h1, HID, 512, g_h2, HID,
                 Wih2, 512, Whh2);
        gbar(base + ++bn);
        update_phase(g_h2, g_c2, bih2, bhh2);
        gbar(base + ++bn);

        // LSTM3: A = [h2 | h3], K=1024
        gemm_mma(S, t, g_part, 2048, 16, 32, 8,
                 nullptr, nullptr, 0, 0,
                 g_h2, HID, 512, g_h3, HID,
                 Wih3, 512, Whh3);
        gbar(base + ++bn);
        update_phase(g_h3, g_c3, bih3, bhh3);
        gbar(base + ++bn);

        // attention from new h3
        attend_phase(S, key, value, flens, Wq, bq);
        gbar(base + ++bn);

        // mlp: A = [h3 | ctx], W = Wmlp, K=640, N=512, split-K 8 (32 jobs)
        gemm_mma(S, t, g_mpart, HID, 4, 20, 8,
                 nullptr, nullptr, 0, 0,
                 g_h3, HID, 512, g_ctx, ATT,
                 Wmlp, 640, nullptr);
        gbar(base + ++bn);

        // combine + LeakyReLU + tied projection + log-softmax
        proj_phase(S, emb, bproj, bmlp, out, t, ml);
        // no grid barrier needed: next phase doesn't touch proj's inputs
    }
}

// -------------------- launch ----------------------------------------------------------
extern "C" void kernel_launch(void* const* d_in, const int* in_sizes, int n_in,
                              void* d_out, int out_size)
{
    const float* key        = (const float*)d_in[0];
    const float* value      = (const float*)d_in[1];
    const int*   Yinput     = (const int*)d_in[2];
    const int*   frame_lens = (const int*)d_in[3];
    // d_in[4] = max_len scalar; derived from out_size instead
    const float* emb   = (const float*)d_in[5];
    const float* Wq    = (const float*)d_in[6];
    const float* bq    = (const float*)d_in[7];
    const float* Wih1  = (const float*)d_in[8];
    const float* Whh1  = (const float*)d_in[9];
    const float* bih1  = (const float*)d_in[10];
    const float* bhh1  = (const float*)d_in[11];
    const float* Wih2  = (const float*)d_in[12];
    const float* Whh2  = (const float*)d_in[13];
    const float* bih2  = (const float*)d_in[14];
    const float* bhh2  = (const float*)d_in[15];
    const float* Wih3  = (const float*)d_in[16];
    const float* Whh3  = (const float*)d_in[17];
    const float* bih3  = (const float*)d_in[18];
    const float* bhh3  = (const float*)d_in[19];
    const float* Wmlp  = (const float*)d_in[20];
    const float* bmlp  = (const float*)d_in[21];
    const float* bproj = (const float*)d_in[22];
    const float* h00 = (const float*)d_in[23];
    const float* h01 = (const float*)d_in[24];
    const float* h02 = (const float*)d_in[25];
    const float* c00 = (const float*)d_in[26];
    const float* c01 = (const float*)d_in[27];
    const float* c02 = (const float*)d_in[28];

    float* out = (float*)d_out;
    const int ml = out_size / (BATCH * CC);     // 300
    const int ystride = in_sizes[2] / BATCH;    // MAXLEN = 300

    cudaFuncSetAttribute(mega_kernel,
                         cudaFuncAttributeMaxDynamicSharedMemorySize, SMEM_BYTES);

    mega_kernel<<<NBLK, NTHR, SMEM_BYTES>>>(
        key, value, Yinput, frame_lens,
        emb, Wq, bq,
        Wih1, Whh1, bih1, bhh1,
        Wih2, Whh2, bih2, bhh2,
        Wih3, Whh3, bih3, bhh3,
        Wmlp, bmlp, bproj,
        h00, h01, h02, c00, c01, c02,
        out, ml, ystride);
}

// round 7
// speedup vs baseline: 1.0012x; 1.0012x over previous
#include <cuda_runtime.h>
#include <math.h>
#include <stdint.h>

#define BATCH 128
#define HID   512
#define ATT   128
#define TT    256
#define CC    256
#define NEG_SLOPE 0.01f
#define NBLK  128
#define NTHR  512

// pre-split weight buffer layout (virtual K concatenation of [Wih | Whh])
#define W1OFF 0
#define W1LD  1152
#define W2OFF (2048 * 1152)
#define W2LD  1024
#define W3OFF (W2OFF + 2048 * 1024)
#define W3LD  1024
#define WMOFF (W3OFF + 2048 * 1024)
#define WMLD  640
#define WTOT  (WMOFF + 512 * 640)

// -------------------- device-global scratch (no allocs allowed) ----------------
__device__ float g_h1[BATCH * HID];
__device__ float g_c1[BATCH * HID];
__device__ float g_h2[BATCH * HID];
__device__ float g_c2[BATCH * HID];
__device__ float g_h3[BATCH * HID];
__device__ float g_c3[BATCH * HID];
__device__ float g_ctx[BATCH * ATT];
__device__ float g_part[8 * BATCH * 2048];   // split-K partials, gate GEMMs
__device__ float g_mpart[8 * BATCH * HID];   // split-K partials, mlp GEMM
__device__ float g_whi[WTOT];                // pre-split tf32 hi of weights
__device__ float g_wlo[WTOT];                // pre-split tf32 lo of weights
__device__ unsigned g_ctr;                   // barrier arrivals (monotonic)
__device__ unsigned g_epoch;                 // released epochs  (monotonic)

// -------------------- shared memory ----------------------------------------------
struct GemmSmem { float ahi[4096]; float alo[4096]; float whi[4096]; float wlo[4096]; };
struct AttSmem  { float hs[NTHR]; float pr[NTHR]; float qs[ATT]; float at[TT]; float red[16]; };
struct ProjSmem { float ms[HID]; float pr[NTHR]; float red[16]; };
union SmemAll { GemmSmem g; AttSmem a; ProjSmem p; };
#define SMEM_BYTES (sizeof(SmemAll) + 1024)

// -------------------- tf32 helpers -------------------------------------------------
__device__ __forceinline__ float tf32_rna(float x) {
    uint32_t r; asm("cvt.rna.tf32.f32 %0, %1;" : "=r"(r) : "f"(x));
    return __uint_as_float(r);
}

// m16n8k8 tf32 mma: D += A x B
__device__ __forceinline__ void mma8(float* d, const uint32_t* a, const uint32_t* b) {
    asm volatile(
        "mma.sync.aligned.m16n8k8.row.col.f32.tf32.tf32.f32 "
        "{%0,%1,%2,%3}, {%4,%5,%6,%7}, {%8,%9}, {%0,%1,%2,%3};"
        : "+f"(d[0]), "+f"(d[1]), "+f"(d[2]), "+f"(d[3])
        : "r"(a[0]), "r"(a[1]), "r"(a[2]), "r"(a[3]), "r"(b[0]), "r"(b[1]));
}

// smem layout: addr(m,k) = m*32 + ((k + 4*(m&7) + ((m>>3)&3)) & 31)
// conflict-free for 32-consecutive-row scalar stores AND 8row x 4col frag loads.
__device__ __forceinline__ int swz(int m, int k) {
    return (m << 5) + ((k + ((m & 7) << 2) + ((m >> 3) & 3)) & 31);
}

// -------------------- grid barrier (single counter + epoch) -------------------------
__device__ __forceinline__ void st_rel(unsigned* p, unsigned v) {
    asm volatile("st.release.gpu.u32 [%0], %1;" :: "l"(p), "r"(v) : "memory");
}
__device__ __forceinline__ unsigned ld_acq(const unsigned* p) {
    unsigned v;
    asm volatile("ld.acquire.gpu.u32 %0, [%1];" : "=r"(v) : "l"(p) : "memory");
    return v;
}
__device__ __forceinline__ void gbar(unsigned goal) {   // goal = absolute epoch
    __syncthreads();
    if (threadIdx.x == 0) {
        unsigned v;
        asm volatile("atom.add.acq_rel.gpu.u32 %0, [%1], %2;"
                     : "=r"(v) : "l"(&g_ctr), "r"(1u) : "memory");
        if (v + 1 == goal * NBLK) st_rel(&g_epoch, goal);
        while (ld_acq(&g_epoch) < goal) __nanosleep(16);
    }
    __syncthreads();
}

// -------------------- reductions (512 threads = 16 warps) ---------------------------
__device__ __forceinline__ float warpMax(float v) {
    #pragma unroll
    for (int o = 16; o; o >>= 1) v = fmaxf(v, __shfl_xor_sync(0xffffffffu, v, o));
    return v;
}
__device__ __forceinline__ float warpSum(float v) {
    #pragma unroll
    for (int o = 16; o; o >>= 1) v += __shfl_xor_sync(0xffffffffu, v, o);
    return v;
}
__device__ float blockMax(float v, float* red) {
    v = warpMax(v);
    if ((threadIdx.x & 31) == 0) red[threadIdx.x >> 5] = v;
    __syncthreads();
    if (threadIdx.x < 32) {
        float x = (threadIdx.x < 16) ? red[threadIdx.x] : -3.4e38f;
        x = warpMax(x);
        if (threadIdx.x == 0) red[0] = x;
    }
    __syncthreads();
    float r = red[0];
    __syncthreads();
    return r;
}
__device__ float blockSum(float v, float* red) {
    v = warpSum(v);
    if ((threadIdx.x & 31) == 0) red[threadIdx.x >> 5] = v;
    __syncthreads();
    if (threadIdx.x < 32) {
        float x = (threadIdx.x < 16) ? red[threadIdx.x] : 0.f;
        x = warpSum(x);
        if (threadIdx.x == 0) red[0] = x;
    }
    __syncthreads();
    float r = red[0];
    __syncthreads();
    return r;
}

// -------------------- one-time weight hi/lo split ------------------------------------
__device__ void split_seg(size_t dbase, int dld, int dcol,
                          const float* __restrict__ src, int rows, int cols)
{
    const int gid = blockIdx.x * NTHR + threadIdx.x;
    const int total = (rows * cols) >> 2;
    const int c4 = cols >> 2;
    for (int i = gid; i < total; i += NBLK * NTHR) {
        const int r = i / c4;
        const int c = (i - r * c4) << 2;
        const float4 v = *reinterpret_cast<const float4*>(src + (size_t)r * cols + c);
        float4 h, l;
        h.x = tf32_rna(v.x); l.x = tf32_rna(v.x - h.x);
        h.y = tf32_rna(v.y); l.y = tf32_rna(v.y - h.y);
        h.z = tf32_rna(v.z); l.z = tf32_rna(v.z - h.z);
        h.w = tf32_rna(v.w); l.w = tf32_rna(v.w - h.w);
        const size_t o = dbase + (size_t)r * dld + dcol + c;
        *reinterpret_cast<float4*>(g_whi + o) = h;
        *reinterpret_cast<float4*>(g_wlo + o) = l;
    }
}

// -------------------- tensor-core GEMM phase (3xTF32, 4x4 warp grid) -----------------
// part[ks][BATCH][partN] = A(128 x Kslice) @ W(128 x Kslice)^T per (n-tile, ks) job.
// A virtual row m: k<s0: emb[Yin[m*ystride+t]] ; k<s1: p1 (ld l1) ; else p2 (ld l2).
// W: pre-split rows at g_whi/g_wlo + woff, leading dim wld.
__device__ void gemm_mma(SmemAll& SS, int t,
    float* part, int partN, int ntN, int nchunks, int ksplit,
    const float* emb, const int* Yin, int ystride, int s0,
    const float* p1, int l1, int s1,
    const float* p2, int l2,
    size_t woff, int wld)
{
    const int bid = blockIdx.x;
    if (bid >= ntN * ksplit) return;
    float* Ahi = SS.g.ahi; float* Alo = SS.g.alo;
    float* Whi = SS.g.whi; float* Wlo = SS.g.wlo;

    const int tid = threadIdx.x;
    const int nt = bid / ksplit, ks = bid % ksplit;
    const int N0 = nt * 128;
    const int q = nchunks / ksplit, r = nchunks % ksplit;
    const int cnt = q + (ks < r ? 1 : 0);
    const int c0 = ks * q + (ks < r ? ks : r);

    const int lm  = tid & 127;          // staging row (A: m, W: n-local)
    const int lkg = (tid >> 7) << 3;    // staging k offset (8 floats)
    const int lane = tid & 31;
    const int wid = tid >> 5;
    const int wm = wid & 3;             // warp M-tile (32 rows)
    const int wn = wid >> 2;            // warp N-tile (32 cols)
    const int fr = lane >> 2;
    const int fc = lane & 3;

    const float* wsh = g_whi + woff + (size_t)(N0 + lm) * wld;
    const float* wsl = g_wlo + woff + (size_t)(N0 + lm) * wld;

    float acc[2][4][4];
    #pragma unroll
    for (int i = 0; i < 2; i++)
        #pragma unroll
        for (int j = 0; j < 4; j++)
            #pragma unroll
            for (int x = 0; x < 4; x++) acc[i][j][x] = 0.f;

    // register prefetch buffers
    float4 ar0, ar1, wh0, wh1, wl0, wl1;
    {
        const int gk = c0 * 32 + lkg;
        const float* ap;
        if (gk < s0)      ap = emb + (size_t)Yin[lm * ystride + t] * HID + gk;
        else if (gk < s1) ap = p1 + (size_t)lm * l1 + (gk - s0);
        else              ap = p2 + (size_t)lm * l2 + (gk - s1);
        ar0 = *reinterpret_cast<const float4*>(ap);
        ar1 = *reinterpret_cast<const float4*>(ap + 4);
        wh0 = *reinterpret_cast<const float4*>(wsh + gk);
        wh1 = *reinterpret_cast<const float4*>(wsh + gk + 4);
        wl0 = *reinterpret_cast<const float4*>(wsl + gk);
        wl1 = *reinterpret_cast<const float4*>(wsl + gk + 4);
    }

    const int S = ((lm & 7) << 2) + ((lm >> 3) & 3);
    const int mb = lm << 5;

    for (int cc = 0; cc < cnt; cc++) {
        __syncthreads();
        {
            const float va[8] = {ar0.x, ar0.y, ar0.z, ar0.w, ar1.x, ar1.y, ar1.z, ar1.w};
            const float vh[8] = {wh0.x, wh0.y, wh0.z, wh0.w, wh1.x, wh1.y, wh1.z, wh1.w};
            const float vl[8] = {wl0.x, wl0.y, wl0.z, wl0.w, wl1.x, wl1.y, wl1.z, wl1.w};
            #pragma unroll
            for (int i = 0; i < 8; i++) {
                const int col = (lkg + i + S) & 31;
                const float h = tf32_rna(va[i]);
                Ahi[mb + col] = h;
                Alo[mb + col] = tf32_rna(va[i] - h);
                Whi[mb + col] = vh[i];
                Wlo[mb + col] = vl[i];
            }
        }
        __syncthreads();

        if (cc + 1 < cnt) {
            const int gk = (c0 + cc + 1) * 32 + lkg;
            const float* ap;
            if (gk < s0)      ap = emb + (size_t)Yin[lm * ystride + t] * HID + gk;
            else if (gk < s1) ap = p1 + (size_t)lm * l1 + (gk - s0);
            else              ap = p2 + (size_t)lm * l2 + (gk - s1);
            ar0 = *reinterpret_cast<const float4*>(ap);
            ar1 = *reinterpret_cast<const float4*>(ap + 4);
            wh0 = *reinterpret_cast<const float4*>(wsh + gk);
            wh1 = *reinterpret_cast<const float4*>(wsh + gk + 4);
            wl0 = *reinterpret_cast<const float4*>(wsl + gk);
            wl1 = *reinterpret_cast<const float4*>(wsl + gk + 4);
        }

        #pragma unroll
        for (int kk = 0; kk < 4; kk++) {
            const int k0 = kk * 8;
            uint32_t ah[2][4], al[2][4];
            #pragma unroll
            for (int m2 = 0; m2 < 2; m2++) {
                const int ra = 32 * wm + 16 * m2 + fr;
                ah[m2][0] = __float_as_uint(Ahi[swz(ra,     k0 + fc)]);
                ah[m2][1] = __float_as_uint(Ahi[swz(ra + 8, k0 + fc)]);
                ah[m2][2] = __float_as_uint(Ahi[swz(ra,     k0 + fc + 4)]);
                ah[m2][3] = __float_as_uint(Ahi[swz(ra + 8, k0 + fc + 4)]);
                al[m2][0] = __float_as_uint(Alo[swz(ra,     k0 + fc)]);
                al[m2][1] = __float_as_uint(Alo[swz(ra + 8, k0 + fc)]);
                al[m2][2] = __float_as_uint(Alo[swz(ra,     k0 + fc + 4)]);
                al[m2][3] = __float_as_uint(Alo[swz(ra + 8, k0 + fc + 4)]);
            }
            #pragma unroll
            for (int j = 0; j < 4; j++) {
                const int nb = 32 * wn + 8 * j + fr;
                uint32_t bh[2], bl[2];
                bh[0] = __float_as_uint(Whi[swz(nb, k0 + fc)]);
                bh[1] = __float_as_uint(Whi[swz(nb, k0 + fc + 4)]);
                bl[0] = __float_as_uint(Wlo[swz(nb, k0 + fc)]);
                bl[1] = __float_as_uint(Wlo[swz(nb, k0 + fc + 4)]);
                mma8(acc[0][j], ah[0], bh);
                mma8(acc[0][j], ah[0], bl);
                mma8(acc[0][j], al[0], bh);
                mma8(acc[1][j], ah[1], bh);
                mma8(acc[1][j], ah[1], bl);
                mma8(acc[1][j], al[1], bh);
            }
        }
    }

    // epilogue: write split-K partials
    #pragma unroll
    for (int m2 = 0; m2 < 2; m2++)
        #pragma unroll
        for (int j = 0; j < 4; j++) {
            const int row0 = 32 * wm + 16 * m2 + fr;
            const int col = N0 + 32 * wn + 8 * j + 2 * fc;
            float* op0 = part + (size_t)(ks * BATCH + row0) * partN + col;
            float* op1 = part + (size_t)(ks * BATCH + row0 + 8) * partN + col;
            *reinterpret_cast<float2*>(op0) = make_float2(acc[m2][j][0], acc[m2][j][1]);
            *reinterpret_cast<float2*>(op1) = make_float2(acc[m2][j][2], acc[m2][j][3]);
        }
}

// -------------------- LSTM pointwise update (block = batch row) ---------------------
__device__ void update_phase(float* h, float* c, const float* bih, const float* bhh)
{
    const int b = blockIdx.x;
    const int j = threadIdx.x;   // 0..511 == HID
    float gi = bih[j] + bhh[j];
    float gf = bih[j + 512] + bhh[j + 512];
    float gg = bih[j + 1024] + bhh[j + 1024];
    float go = bih[j + 1536] + bhh[j + 1536];
    #pragma unroll
    for (int ks = 0; ks < 8; ks++) {
        const float* pk = g_part + (size_t)(ks * BATCH + b) * 2048;
        gi += pk[j];
        gf += pk[j + 512];
        gg += pk[j + 1024];
        go += pk[j + 1536];
    }
    const float ig = 1.f / (1.f + expf(-gi));
    const float fg = 1.f / (1.f + expf(-gf));
    const float og = 1.f / (1.f + expf(-go));
    const float gv = tanhf(gg);
    const int idx = b * HID + j;
    const float cn = fg * c[idx] + ig * gv;
    c[idx] = cn;
    h[idx] = og * tanhf(cn);
}

// -------------------- fused attention (block = batch row, 512 thr) ------------------
__device__ void attend_phase(SmemAll& SS, const float* key, const float* value,
                             const int* flens, const float* Wq, const float* bq)
{
    AttSmem& A = SS.a;
    const int b = blockIdx.x;
    const int tid = threadIdx.x;

    A.hs[tid] = g_h3[b * HID + tid];
    __syncthreads();

    // q = h3 @ Wq^T + bq : 4 threads per output a, 128 k each
    {
        const int a = tid & 127;
        const int p = tid >> 7;
        const float* wr = Wq + (size_t)a * HID + p * 128;
        const float* hr = A.hs + p * 128;
        float s = 0.f;
        #pragma unroll 8
        for (int k = 0; k < 128; k += 4) {
            const float4 w = *reinterpret_cast<const float4*>(wr + k);
            s += w.x * hr[k] + w.y * hr[k + 1] + w.z * hr[k + 2] + w.w * hr[k + 3];
        }
        A.pr[tid] = s;
    }
    __syncthreads();
    if (tid < ATT)
        A.qs[tid] = A.pr[tid] + A.pr[tid + 128] + A.pr[tid + 256] + A.pr[tid + 384] + bq[tid];
    __syncthreads();

    // energy: 2 threads per position t (64 a each)
    {
        const int tp = tid & 255;
        const int hf = tid >> 8;
        const float* kp = key + (size_t)b * ATT * TT + tp;
        float e = 0.f;
        #pragma unroll 8
        for (int a = 0; a < 64; a++) e += A.qs[hf * 64 + a] * kp[(size_t)(hf * 64 + a) * TT];
        A.pr[tid] = e;
    }
    __syncthreads();

    const int flen = flens[b] >> 3;
    const float ev = (tid < 256) ? (A.pr[tid] + A.pr[tid + 256]) : -3.4e38f;
    const float mx = blockMax(ev, A.red);
    const float w = (tid < 256 && tid < flen) ? expf(ev - mx) : 0.f;
    const float sm = blockSum(w, A.red);
    if (tid < 256) A.at[tid] = w / sm;
    __syncthreads();

    // ctx = attn @ value : 4 threads per output v, 64 t each
    {
        const int v = tid & 127;
        const int p = tid >> 7;
        const float* vp = value + (size_t)b * TT * ATT + (size_t)(p * 64) * ATT + v;
        float cs = 0.f;
        #pragma unroll 8
        for (int t2 = 0; t2 < 64; t2++) cs += A.at[p * 64 + t2] * vp[(size_t)t2 * ATT];
        A.pr[tid] = cs;
    }
    __syncthreads();
    if (tid < ATT)
        g_ctx[b * ATT + tid] = A.pr[tid] + A.pr[tid + 128] + A.pr[tid + 256] + A.pr[tid + 384];
    __syncthreads();
}

// -------------------- mlp-combine + projection + log-softmax ------------------------
__device__ void proj_phase(SmemAll& SS, const float* emb, const float* bproj,
                           const float* bmlp, float* out, int t, int ml)
{
    ProjSmem& P = SS.p;
    const int b = blockIdx.x;
    const int tid = threadIdx.x;

    // combine mlp split-K partials + bias + LeakyReLU (fixed order => deterministic)
    {
        float s = bmlp[tid];
        #pragma unroll
        for (int ks = 0; ks < 8; ks++)
            s += g_mpart[((size_t)(ks * BATCH) + b) * HID + tid];
        P.ms[tid] = (s >= 0.f) ? s : NEG_SLOPE * s;
    }
    __syncthreads();

    // logits: 2 threads per class c (256 k each)
    {
        const int c = tid & 255;
        const int hf = tid >> 8;
        const float* er = emb + (size_t)c * HID + hf * 256;
        const float* mr = P.ms + hf * 256;
        float s = 0.f;
        #pragma unroll 8
        for (int k = 0; k < 256; k += 4) {
            const float4 w = *reinterpret_cast<const float4*>(er + k);
            s += w.x * mr[k] + w.y * mr[k + 1] + w.z * mr[k + 2] + w.w * mr[k + 3];
        }
        P.pr[tid] = s;
    }
    __syncthreads();

    const float lv = (tid < 256) ? (P.pr[tid] + P.pr[tid + 256] + bproj[tid]) : -3.4e38f;
    const float mx = blockMax(lv, P.red);
    const float ex = (tid < 256) ? expf(lv - mx) : 0.f;
    const float sm = blockSum(ex, P.red);
    if (tid < 256)
        out[((size_t)b * ml + t) * CC + tid] = lv - mx - logf(sm);
    __syncthreads();
}

// -------------------- persistent megakernel -----------------------------------------
__global__ __launch_bounds__(NTHR, 1) void mega_kernel(
    const float* key, const float* value, const int* Yin, const int* flens,
    const float* emb, const float* Wq, const float* bq,
    const float* Wih1, const float* Whh1, const float* bih1, const float* bhh1,
    const float* Wih2, const float* Whh2, const float* bih2, const float* bhh2,
    const float* Wih3, const float* Whh3, const float* bih3, const float* bhh3,
    const float* Wmlp, const float* bmlp, const float* bproj,
    const float* h00, const float* h01, const float* h02,
    const float* c00, const float* c01, const float* c02,
    float* out, int ml, int ystride)
{
    extern __shared__ char dyn_smem[];
    char* sb = (char*)((((uintptr_t)dyn_smem) + 1023) & ~(uintptr_t)1023);
    SmemAll& S = *reinterpret_cast<SmemAll*>(sb);

    const int tid = threadIdx.x;
    const unsigned base = ld_acq(&g_epoch);   // monotonic across replays
    unsigned bn = 0;

    // ---- one-time (per launch) weight hi/lo pre-split ----
    split_seg(W1OFF, W1LD, 0,   Wih1, 2048, 640);
    split_seg(W1OFF, W1LD, 640, Whh1, 2048, 512);
    split_seg(W2OFF, W2LD, 0,   Wih2, 2048, 512);
    split_seg(W2OFF, W2LD, 512, Whh2, 2048, 512);
    split_seg(W3OFF, W3LD, 0,   Wih3, 2048, 512);
    split_seg(W3OFF, W3LD, 512, Whh3, 2048, 512);
    split_seg(WMOFF, WMLD, 0,   Wmlp, 512, 640);

    // init state (broadcast initial h/c); 128*512 threads == BATCH*HID
    {
        const int idx = blockIdx.x * NTHR + tid;
        const int j = idx & 511;
        g_h1[idx] = h00[j]; g_h2[idx] = h01[j]; g_h3[idx] = h02[j];
        g_c1[idx] = c00[j]; g_c2[idx] = c01[j]; g_c3[idx] = c02[j];
    }
    gbar(base + ++bn);
    attend_phase(S, key, value, flens, Wq, bq);
    gbar(base + ++bn);

    for (int t = 0; t < ml; t++) {
        // LSTM1: A = [emb[y_t] | ctx | h1], K=1152
        gemm_mma(S, t, g_part, 2048, 16, 36, 8,
                 emb, Yin, ystride, 512,
                 g_ctx, ATT, 640, g_h1, HID,
                 W1OFF, W1LD);
        gbar(base + ++bn);
        update_phase(g_h1, g_c1, bih1, bhh1);
        gbar(base + ++bn);

        // LSTM2: A = [h1 | h2], K=1024
        gemm_mma(S, t, g_part, 2048, 16, 32, 8,
                 nullptr, nullptr, 0, 0,
                 g_h1, HID, 512, g_h2, HID,
                 W2OFF, W2LD);
        gbar(base + ++bn);
        update_phase(g_h2, g_c2, bih2, bhh2);
        gbar(base + ++bn);

        // LSTM3: A = [h2 | h3], K=1024
        gemm_mma(S, t, g_part, 2048, 16, 32, 8,
                 nullptr, nullptr, 0, 0,
                 g_h2, HID, 512, g_h3, HID,
                 W3OFF, W3LD);
        gbar(base + ++bn);
        update_phase(g_h3, g_c3, bih3, bhh3);
        gbar(base + ++bn);

        // attention from new h3
        attend_phase(S, key, value, flens, Wq, bq);
        gbar(base + ++bn);

        // mlp: A = [h3 | ctx], K=640, N=512, split-K 8 (32 jobs)
        gemm_mma(S, t, g_mpart, 512, 4, 20, 8,
                 nullptr, nullptr, 0, 0,
                 g_h3, HID, 512, g_ctx, ATT,
                 WMOFF, WMLD);
        gbar(base + ++bn);

        // combine + LeakyReLU + tied projection + log-softmax
        proj_phase(S, emb, bproj, bmlp, out, t, ml);
        // no grid barrier: proj writes only `out`; next phase touches none of it
    }
}

// -------------------- launch ----------------------------------------------------------
extern "C" void kernel_launch(void* const* d_in, const int* in_sizes, int n_in,
                              void* d_out, int out_size)
{
    const float* key        = (const float*)d_in[0];
    const float* value      = (const float*)d_in[1];
    const int*   Yinput     = (const int*)d_in[2];
    const int*   frame_lens = (const int*)d_in[3];
    // d_in[4] = max_len scalar; derived from out_size instead
    const float* emb   = (const float*)d_in[5];
    const float* Wq    = (const float*)d_in[6];
    const float* bq    = (const float*)d_in[7];
    const float* Wih1  = (const float*)d_in[8];
    const float* Whh1  = (const float*)d_in[9];
    const float* bih1  = (const float*)d_in[10];
    const float* bhh1  = (const float*)d_in[11];
    const float* Wih2  = (const float*)d_in[12];
    const float* Whh2  = (const float*)d_in[13];
    const float* bih2  = (const float*)d_in[14];
    const float* bhh2  = (const float*)d_in[15];
    const float* Wih3  = (const float*)d_in[16];
    const float* Whh3  = (const float*)d_in[17];
    const float* bih3  = (const float*)d_in[18];
    const float* bhh3  = (const float*)d_in[19];
    const float* Wmlp  = (const float*)d_in[20];
    const float* bmlp  = (const float*)d_in[21];
    const float* bproj = (const float*)d_in[22];
    const float* h00 = (const float*)d_in[23];
    const float* h01 = (const float*)d_in[24];
    const float* h02 = (const float*)d_in[25];
    const float* c00 = (const float*)d_in[26];
    const float* c01 = (const float*)d_in[27];
    const float* c02 = (const float*)d_in[28];

    float* out = (float*)d_out;
    const int ml = out_size / (BATCH * CC);     // 300
    const int ystride = in_sizes[2] / BATCH;    // MAXLEN = 300

    cudaFuncSetAttribute(mega_kernel,
                         cudaFuncAttributeMaxDynamicSharedMemorySize, SMEM_BYTES);

    mega_kernel<<<NBLK, NTHR, SMEM_BYTES>>>(
        key, value, Yinput, frame_lens,
        emb, Wq, bq,
        Wih1, Whh1, bih1, bhh1,
        Wih2, Whh2, bih2, bhh2,
        Wih3, Whh3, bih3, bhh3,
        Wmlp, bmlp, bproj,
        h00, h01, h02, c00, c01, c02,
        out, ml, ystride);
}

// round 8
// speedup vs baseline: 1.1811x; 1.1797x over previous
#include <cuda_runtime.h>
#include <math.h>
#include <stdint.h>

#define BATCH 128
#define HID   512
#define ATT   128
#define TT    256
#define CC    256
#define NEG_SLOPE 0.01f
#define NBLK  128
#define NTHR  512

// pre-split weight buffer layout (virtual K concatenation of [Wih | Whh])
#define W1OFF 0
#define W1LD  1152
#define W2OFF (2048 * 1152)
#define W2LD  1024
#define W3OFF (W2OFF + 2048 * 1024)
#define W3LD  1024
#define WMOFF (W3OFF + 2048 * 1024)
#define WMLD  640
#define WTOT  (WMOFF + 512 * 640)

// -------------------- device-global scratch (no allocs allowed) ----------------
__device__ float g_h1[BATCH * HID];
__device__ float g_c1[BATCH * HID];
__device__ float g_h2[BATCH * HID];
__device__ float g_c2[BATCH * HID];
__device__ float g_h3[BATCH * HID];
__device__ float g_c3[BATCH * HID];
__device__ float g_ctx[BATCH * ATT];
__device__ float g_part[8 * BATCH * 2048];   // split-K partials, gate GEMMs
__device__ float g_mpart[8 * BATCH * HID];   // split-K partials, mlp GEMM
__device__ float g_whi[WTOT];                // pre-split tf32 hi of weights
__device__ float g_wlo[WTOT];                // pre-split tf32 lo of weights
__device__ unsigned g_ctr;                   // barrier arrivals (monotonic)
__device__ unsigned g_epoch;                 // released epochs  (monotonic)

// -------------------- shared memory ----------------------------------------------
struct GemmSmem { float ahi[4096]; float alo[4096]; float whi[4096]; float wlo[4096]; };
struct AttSmem  { float hs[NTHR]; float pr[NTHR]; float qs[ATT]; float at[TT]; float red[16]; };
struct ProjSmem { float ms[HID]; float pr[NTHR]; float red[16]; };
union SmemAll { GemmSmem g; AttSmem a; ProjSmem p; };
#define SMEM_BYTES (sizeof(SmemAll) + 1024)

// -------------------- tf32 helpers -------------------------------------------------
__device__ __forceinline__ float tf32_rna(float x) {
    uint32_t r; asm("cvt.rna.tf32.f32 %0, %1;" : "=r"(r) : "f"(x));
    return __uint_as_float(r);
}

// m16n8k8 tf32 mma: D += A x B
__device__ __forceinline__ void mma8(float* d, const uint32_t* a, const uint32_t* b) {
    asm volatile(
        "mma.sync.aligned.m16n8k8.row.col.f32.tf32.tf32.f32 "
        "{%0,%1,%2,%3}, {%4,%5,%6,%7}, {%8,%9}, {%0,%1,%2,%3};"
        : "+f"(d[0]), "+f"(d[1]), "+f"(d[2]), "+f"(d[3])
        : "r"(a[0]), "r"(a[1]), "r"(a[2]), "r"(a[3]), "r"(b[0]), "r"(b[1]));
}

// smem layout: addr(m,k) = m*32 + ((k + 4*(m&7) + ((m>>3)&3)) & 31)
// conflict-free for 32-consecutive-row scalar stores AND 8row x 4col frag loads.
__device__ __forceinline__ int swz(int m, int k) {
    return (m << 5) + ((k + ((m & 7) << 2) + ((m >> 3) & 3)) & 31);
}

// -------------------- grid barrier (single counter + epoch, tight poll) -------------
__device__ __forceinline__ void st_rel(unsigned* p, unsigned v) {
    asm volatile("st.release.gpu.u32 [%0], %1;" :: "l"(p), "r"(v) : "memory");
}
__device__ __forceinline__ unsigned ld_acq(const unsigned* p) {
    unsigned v;
    asm volatile("ld.acquire.gpu.u32 %0, [%1];" : "=r"(v) : "l"(p) : "memory");
    return v;
}
__device__ __forceinline__ void gbar(unsigned goal) {   // goal = absolute epoch
    __syncthreads();
    if (threadIdx.x == 0) {
        unsigned v;
        asm volatile("atom.add.acq_rel.gpu.u32 %0, [%1], %2;"
                     : "=r"(v) : "l"(&g_ctr), "r"(1u) : "memory");
        if (v + 1 == goal * NBLK) st_rel(&g_epoch, goal);
        while (ld_acq(&g_epoch) < goal) { }   // tight poll, no nanosleep
    }
    __syncthreads();
}

// -------------------- reductions (512 threads = 16 warps) ---------------------------
__device__ __forceinline__ float warpMax(float v) {
    #pragma unroll
    for (int o = 16; o; o >>= 1) v = fmaxf(v, __shfl_xor_sync(0xffffffffu, v, o));
    return v;
}
__device__ __forceinline__ float warpSum(float v) {
    #pragma unroll
    for (int o = 16; o; o >>= 1) v += __shfl_xor_sync(0xffffffffu, v, o);
    return v;
}
__device__ float blockMax(float v, float* red) {
    v = warpMax(v);
    if ((threadIdx.x & 31) == 0) red[threadIdx.x >> 5] = v;
    __syncthreads();
    if (threadIdx.x < 32) {
        float x = (threadIdx.x < 16) ? red[threadIdx.x] : -3.4e38f;
        x = warpMax(x);
        if (threadIdx.x == 0) red[0] = x;
    }
    __syncthreads();
    float r = red[0];
    __syncthreads();
    return r;
}
__device__ float blockSum(float v, float* red) {
    v = warpSum(v);
    if ((threadIdx.x & 31) == 0) red[threadIdx.x >> 5] = v;
    __syncthreads();
    if (threadIdx.x < 32) {
        float x = (threadIdx.x < 16) ? red[threadIdx.x] : 0.f;
        x = warpSum(x);
        if (threadIdx.x == 0) red[0] = x;
    }
    __syncthreads();
    float r = red[0];
    __syncthreads();
    return r;
}

// -------------------- one-time weight hi/lo split ------------------------------------
__device__ void split_seg(size_t dbase, int dld, int dcol,
                          const float* __restrict__ src, int rows, int cols)
{
    const int gid = blockIdx.x * NTHR + threadIdx.x;
    const int total = (rows * cols) >> 2;
    const int c4 = cols >> 2;
    for (int i = gid; i < total; i += NBLK * NTHR) {
        const int r = i / c4;
        const int c = (i - r * c4) << 2;
        const float4 v = *reinterpret_cast<const float4*>(src + (size_t)r * cols + c);
        float4 h, l;
        h.x = tf32_rna(v.x); l.x = tf32_rna(v.x - h.x);
        h.y = tf32_rna(v.y); l.y = tf32_rna(v.y - h.y);
        h.z = tf32_rna(v.z); l.z = tf32_rna(v.z - h.z);
        h.w = tf32_rna(v.w); l.w = tf32_rna(v.w - h.w);
        const size_t o = dbase + (size_t)r * dld + dcol + c;
        *reinterpret_cast<float4*>(g_whi + o) = h;
        *reinterpret_cast<float4*>(g_wlo + o) = l;
    }
}

// -------------------- tensor-core GEMM job (3xTF32, 4x4 warp grid) -------------------
// part[ks][BATCH][partN] = A(128 x Kslice) @ W(128 x Kslice)^T for job jid.
// A virtual row m: k<s0: emb[Yin[m*ystride+t]] ; k<s1: p1 (ld l1) ; else p2 (ld l2).
// W: pre-split rows at g_whi/g_wlo + woff, leading dim wld.
__device__ void gemm_mma(SmemAll& SS, int jid, int t,
    float* part, int partN, int ntN, int nchunks, int ksplit,
    const float* emb, const int* Yin, int ystride, int s0,
    const float* p1, int l1, int s1,
    const float* p2, int l2,
    size_t woff, int wld)
{
    if (jid < 0 || jid >= ntN * ksplit) return;
    float* Ahi = SS.g.ahi; float* Alo = SS.g.alo;
    float* Whi = SS.g.whi; float* Wlo = SS.g.wlo;

    const int tid = threadIdx.x;
    const int nt = jid / ksplit, ks = jid % ksplit;
    const int N0 = nt * 128;
    const int q = nchunks / ksplit, r = nchunks % ksplit;
    const int cnt = q + (ks < r ? 1 : 0);
    const int c0 = ks * q + (ks < r ? ks : r);

    const int lm  = tid & 127;          // staging row (A: m, W: n-local)
    const int lkg = (tid >> 7) << 3;    // staging k offset (8 floats)
    const int lane = tid & 31;
    const int wid = tid >> 5;
    const int wm = wid & 3;             // warp M-tile (32 rows)
    const int wn = wid >> 2;            // warp N-tile (32 cols)
    const int fr = lane >> 2;
    const int fc = lane & 3;

    const float* wsh = g_whi + woff + (size_t)(N0 + lm) * wld;
    const float* wsl = g_wlo + woff + (size_t)(N0 + lm) * wld;

    float acc[2][4][4];
    #pragma unroll
    for (int i = 0; i < 2; i++)
        #pragma unroll
        for (int j = 0; j < 4; j++)
            #pragma unroll
            for (int x = 0; x < 4; x++) acc[i][j][x] = 0.f;

    // register prefetch buffers
    float4 ar0, ar1, wh0, wh1, wl0, wl1;
    {
        const int gk = c0 * 32 + lkg;
        const float* ap;
        if (gk < s0)      ap = emb + (size_t)Yin[lm * ystride + t] * HID + gk;
        else if (gk < s1) ap = p1 + (size_t)lm * l1 + (gk - s0);
        else              ap = p2 + (size_t)lm * l2 + (gk - s1);
        ar0 = *reinterpret_cast<const float4*>(ap);
        ar1 = *reinterpret_cast<const float4*>(ap + 4);
        wh0 = *reinterpret_cast<const float4*>(wsh + gk);
        wh1 = *reinterpret_cast<const float4*>(wsh + gk + 4);
        wl0 = *reinterpret_cast<const float4*>(wsl + gk);
        wl1 = *reinterpret_cast<const float4*>(wsl + gk + 4);
    }

    const int S = ((lm & 7) << 2) + ((lm >> 3) & 3);
    const int mb = lm << 5;

    for (int cc = 0; cc < cnt; cc++) {
        __syncthreads();
        {
            const float va[8] = {ar0.x, ar0.y, ar0.z, ar0.w, ar1.x, ar1.y, ar1.z, ar1.w};
            const float vh[8] = {wh0.x, wh0.y, wh0.z, wh0.w, wh1.x, wh1.y, wh1.z, wh1.w};
            const float vl[8] = {wl0.x, wl0.y, wl0.z, wl0.w, wl1.x, wl1.y, wl1.z, wl1.w};
            #pragma unroll
            for (int i = 0; i < 8; i++) {
                const int col = (lkg + i + S) & 31;
                const float h = tf32_rna(va[i]);
                Ahi[mb + col] = h;
                Alo[mb + col] = tf32_rna(va[i] - h);
                Whi[mb + col] = vh[i];
                Wlo[mb + col] = vl[i];
            }
        }
        __syncthreads();

        if (cc + 1 < cnt) {
            const int gk = (c0 + cc + 1) * 32 + lkg;
            const float* ap;
            if (gk < s0)      ap = emb + (size_t)Yin[lm * ystride + t] * HID + gk;
            else if (gk < s1) ap = p1 + (size_t)lm * l1 + (gk - s0);
            else              ap = p2 + (size_t)lm * l2 + (gk - s1);
            ar0 = *reinterpret_cast<const float4*>(ap);
            ar1 = *reinterpret_cast<const float4*>(ap + 4);
            wh0 = *reinterpret_cast<const float4*>(wsh + gk);
            wh1 = *reinterpret_cast<const float4*>(wsh + gk + 4);
            wl0 = *reinterpret_cast<const float4*>(wsl + gk);
            wl1 = *reinterpret_cast<const float4*>(wsl + gk + 4);
        }

        #pragma unroll
        for (int kk = 0; kk < 4; kk++) {
            const int k0 = kk * 8;
            uint32_t ah[2][4], al[2][4];
            #pragma unroll
            for (int m2 = 0; m2 < 2; m2++) {
                const int ra = 32 * wm + 16 * m2 + fr;
                ah[m2][0] = __float_as_uint(Ahi[swz(ra,     k0 + fc)]);
                ah[m2][1] = __float_as_uint(Ahi[swz(ra + 8, k0 + fc)]);
                ah[m2][2] = __float_as_uint(Ahi[swz(ra,     k0 + fc + 4)]);
                ah[m2][3] = __float_as_uint(Ahi[swz(ra + 8, k0 + fc + 4)]);
                al[m2][0] = __float_as_uint(Alo[swz(ra,     k0 + fc)]);
                al[m2][1] = __float_as_uint(Alo[swz(ra + 8, k0 + fc)]);
                al[m2][2] = __float_as_uint(Alo[swz(ra,     k0 + fc + 4)]);
                al[m2][3] = __float_as_uint(Alo[swz(ra + 8, k0 + fc + 4)]);
            }
            #pragma unroll
            for (int j = 0; j < 4; j++) {
                const int nb = 32 * wn + 8 * j + fr;
                uint32_t bh[2], bl[2];
                bh[0] = __float_as_uint(Whi[swz(nb, k0 + fc)]);
                bh[1] = __float_as_uint(Whi[swz(nb, k0 + fc + 4)]);
                bl[0] = __float_as_uint(Wlo[swz(nb, k0 + fc)]);
                bl[1] = __float_as_uint(Wlo[swz(nb, k0 + fc + 4)]);
                mma8(acc[0][j], ah[0], bh);
                mma8(acc[0][j], ah[0], bl);
                mma8(acc[0][j], al[0], bh);
                mma8(acc[1][j], ah[1], bh);
                mma8(acc[1][j], ah[1], bl);
                mma8(acc[1][j], al[1], bh);
            }
        }
    }

    // epilogue: write split-K partials
    #pragma unroll
    for (int m2 = 0; m2 < 2; m2++)
        #pragma unroll
        for (int j = 0; j < 4; j++) {
            const int row0 = 32 * wm + 16 * m2 + fr;
            const int col = N0 + 32 * wn + 8 * j + 2 * fc;
            float* op0 = part + (size_t)(ks * BATCH + row0) * partN + col;
            float* op1 = part + (size_t)(ks * BATCH + row0 + 8) * partN + col;
            *reinterpret_cast<float2*>(op0) = make_float2(acc[m2][j][0], acc[m2][j][1]);
            *reinterpret_cast<float2*>(op1) = make_float2(acc[m2][j][2], acc[m2][j][3]);
        }
}

// -------------------- LSTM pointwise update (block = batch row) ---------------------
__device__ void update_phase(float* h, float* c, const float* bih, const float* bhh,
                             int nks)
{
    const int b = blockIdx.x;
    const int j = threadIdx.x;   // 0..511 == HID
    float gi = bih[j] + bhh[j];
    float gf = bih[j + 512] + bhh[j + 512];
    float gg = bih[j + 1024] + bhh[j + 1024];
    float go = bih[j + 1536] + bhh[j + 1536];
    for (int ks = 0; ks < nks; ks++) {
        const float* pk = g_part + (size_t)(ks * BATCH + b) * 2048;
        gi += pk[j];
        gf += pk[j + 512];
        gg += pk[j + 1024];
        go += pk[j + 1536];
    }
    const float ig = 1.f / (1.f + expf(-gi));
    const float fg = 1.f / (1.f + expf(-gf));
    const float og = 1.f / (1.f + expf(-go));
    const float gv = tanhf(gg);
    const int idx = b * HID + j;
    const float cn = fg * c[idx] + ig * gv;
    c[idx] = cn;
    h[idx] = og * tanhf(cn);
}

// -------------------- fused attention (block = batch row, 512 thr) ------------------
__device__ void attend_phase(SmemAll& SS, const float* key, const float* value,
                             const int* flens, const float* Wq, const float* bq)
{
    AttSmem& A = SS.a;
    const int b = blockIdx.x;
    const int tid = threadIdx.x;

    A.hs[tid] = g_h3[b * HID + tid];
    __syncthreads();

    // q = h3 @ Wq^T + bq : 4 threads per output a, 128 k each
    {
        const int a = tid & 127;
        const int p = tid >> 7;
        const float* wr = Wq + (size_t)a * HID + p * 128;
        const float* hr = A.hs + p * 128;
        float s = 0.f;
        #pragma unroll 8
        for (int k = 0; k < 128; k += 4) {
            const float4 w = *reinterpret_cast<const float4*>(wr + k);
            s += w.x * hr[k] + w.y * hr[k + 1] + w.z * hr[k + 2] + w.w * hr[k + 3];
        }
        A.pr[tid] = s;
    }
    __syncthreads();
    if (tid < ATT)
        A.qs[tid] = A.pr[tid] + A.pr[tid + 128] + A.pr[tid + 256] + A.pr[tid + 384] + bq[tid];
    __syncthreads();

    // energy: 2 threads per position t (64 a each)
    {
        const int tp = tid & 255;
        const int hf = tid >> 8;
        const float* kp = key + (size_t)b * ATT * TT + tp;
        float e = 0.f;
        #pragma unroll 8
        for (int a = 0; a < 64; a++) e += A.qs[hf * 64 + a] * kp[(size_t)(hf * 64 + a) * TT];
        A.pr[tid] = e;
    }
    __syncthreads();

    const int flen = flens[b] >> 3;
    const float ev = (tid < 256) ? (A.pr[tid] + A.pr[tid + 256]) : -3.4e38f;
    const float mx = blockMax(ev, A.red);
    const float w = (tid < 256 && tid < flen) ? expf(ev - mx) : 0.f;
    const float sm = blockSum(w, A.red);
    if (tid < 256) A.at[tid] = w / sm;
    __syncthreads();

    // ctx = attn @ value : 4 threads per output v, 64 t each
    {
        const int v = tid & 127;
        const int p = tid >> 7;
        const float* vp = value + (size_t)b * TT * ATT + (size_t)(p * 64) * ATT + v;
        float cs = 0.f;
        #pragma unroll 8
        for (int t2 = 0; t2 < 64; t2++) cs += A.at[p * 64 + t2] * vp[(size_t)t2 * ATT];
        A.pr[tid] = cs;
    }
    __syncthreads();
    if (tid < ATT)
        g_ctx[b * ATT + tid] = A.pr[tid] + A.pr[tid + 128] + A.pr[tid + 256] + A.pr[tid + 384];
    __syncthreads();
}

// -------------------- mlp-combine + projection + log-softmax ------------------------
__device__ void proj_phase(SmemAll& SS, const float* emb, const float* bproj,
                           const float* bmlp, float* out, int t, int ml)
{
    ProjSmem& P = SS.p;
    const int b = blockIdx.x;
    const int tid = threadIdx.x;

    // combine mlp split-K partials + bias + LeakyReLU (fixed order => deterministic)
    {
        float s = bmlp[tid];
        #pragma unroll
        for (int ks = 0; ks < 8; ks++)
            s += g_mpart[((size_t)(ks * BATCH) + b) * HID + tid];
        P.ms[tid] = (s >= 0.f) ? s : NEG_SLOPE * s;
    }
    __syncthreads();

    // logits: 2 threads per class c (256 k each)
    {
        const int c = tid & 255;
        const int hf = tid >> 8;
        const float* er = emb + (size_t)c * HID + hf * 256;
        const float* mr = P.ms + hf * 256;
        float s = 0.f;
        #pragma unroll 8
        for (int k = 0; k < 256; k += 4) {
            const float4 w = *reinterpret_cast<const float4*>(er + k);
            s += w.x * mr[k] + w.y * mr[k + 1] + w.z * mr[k + 2] + w.w * mr[k + 3];
        }
        P.pr[tid] = s;
    }
    __syncthreads();

    const float lv = (tid < 256) ? (P.pr[tid] + P.pr[tid + 256] + bproj[tid]) : -3.4e38f;
    const float mx = blockMax(lv, P.red);
    const float ex = (tid < 256) ? expf(lv - mx) : 0.f;
    const float sm = blockSum(ex, P.red);
    if (tid < 256)
        out[((size_t)b * ml + t) * CC + tid] = lv - mx - logf(sm);
    __syncthreads();
}

// -------------------- persistent megakernel -----------------------------------------
__global__ __launch_bounds__(NTHR, 1) void mega_kernel(
    const float* key, const float* value, const int* Yin, const int* flens,
    const float* emb, const float* Wq, const float* bq,
    const float* Wih1, const float* Whh1, const float* bih1, const float* bhh1,
    const float* Wih2, const float* Whh2, const float* bih2, const float* bhh2,
    const float* Wih3, const float* Whh3, const float* bih3, const float* bhh3,
    const float* Wmlp, const float* bmlp, const float* bproj,
    const float* h00, const float* h01, const float* h02,
    const float* c00, const float* c01, const float* c02,
    float* out, int ml, int ystride)
{
    extern __shared__ char dyn_smem[];
    char* sb = (char*)((((uintptr_t)dyn_smem) + 1023) & ~(uintptr_t)1023);
    SmemAll& S = *reinterpret_cast<SmemAll*>(sb);

    const int tid = threadIdx.x;
    const int bid = blockIdx.x;
    const unsigned base = ld_acq(&g_epoch);   // monotonic across replays
    unsigned bn = 0;

    // ---- one-time (per launch) weight hi/lo pre-split ----
    split_seg(W1OFF, W1LD, 0,   Wih1, 2048, 640);
    split_seg(W1OFF, W1LD, 640, Whh1, 2048, 512);
    split_seg(W2OFF, W2LD, 0,   Wih2, 2048, 512);
    split_seg(W2OFF, W2LD, 512, Whh2, 2048, 512);
    split_seg(W3OFF, W3LD, 0,   Wih3, 2048, 512);
    split_seg(W3OFF, W3LD, 512, Whh3, 2048, 512);
    split_seg(WMOFF, WMLD, 0,   Wmlp, 512, 640);

    // init state (broadcast initial h/c); 128*512 threads == BATCH*HID
    {
        const int idx = bid * NTHR + tid;
        const int j = idx & 511;
        g_h1[idx] = h00[j]; g_h2[idx] = h01[j]; g_h3[idx] = h02[j];
        g_c1[idx] = c00[j]; g_c2[idx] = c01[j]; g_c3[idx] = c02[j];
    }
    gbar(base + ++bn);
    attend_phase(S, key, value, flens, Wq, bq);
    gbar(base + ++bn);

    for (int t = 0; t < ml; t++) {
        // phase X: GEMM1(t) on blocks 0..95 (ksplit 6) || mlp(t-1) on blocks 96..127
        if (bid < 96) {
            gemm_mma(S, bid, t, g_part, 2048, 16, 36, 6,
                     emb, Yin, ystride, 512,
                     g_ctx, ATT, 640, g_h1, HID,
                     W1OFF, W1LD);
        } else if (t > 0) {
            gemm_mma(S, bid - 96, t, g_mpart, 512, 4, 20, 8,
                     nullptr, nullptr, 0, 0,
                     g_h3, HID, 512, g_ctx, ATT,
                     WMOFF, WMLD);
        }
        gbar(base + ++bn);

        // phase Y: upd1(t) + proj(t-1), both on block b = bid
        update_phase(g_h1, g_c1, bih1, bhh1, 6);
        if (t > 0) proj_phase(S, emb, bproj, bmlp, out, t - 1, ml);
        gbar(base + ++bn);

        // LSTM2: A = [h1 | h2], K=1024
        gemm_mma(S, bid, t, g_part, 2048, 16, 32, 8,
                 nullptr, nullptr, 0, 0,
                 g_h1, HID, 512, g_h2, HID,
                 W2OFF, W2LD);
        gbar(base + ++bn);
        update_phase(g_h2, g_c2, bih2, bhh2, 8);
        gbar(base + ++bn);

        // LSTM3: A = [h2 | h3], K=1024
        gemm_mma(S, bid, t, g_part, 2048, 16, 32, 8,
                 nullptr, nullptr, 0, 0,
                 g_h2, HID, 512, g_h3, HID,
                 W3OFF, W3LD);
        gbar(base + ++bn);
        update_phase(g_h3, g_c3, bih3, bhh3, 8);
        gbar(base + ++bn);

        // attention from new h3
        attend_phase(S, key, value, flens, Wq, bq);
        gbar(base + ++bn);
    }

    // drain: mlp(ml-1) then proj(ml-1)
    if (bid >= 96) {
        gemm_mma(S, bid - 96, ml - 1, g_mpart, 512, 4, 20, 8,
                 nullptr, nullptr, 0, 0,
                 g_h3, HID, 512, g_ctx, ATT,
                 WMOFF, WMLD);
    }
    gbar(base + ++bn);
    proj_phase(S, emb, bproj, bmlp, out, ml - 1, ml);
}

// -------------------- launch ----------------------------------------------------------
extern "C" void kernel_launch(void* const* d_in, const int* in_sizes, int n_in,
                              void* d_out, int out_size)
{
    const float* key        = (const float*)d_in[0];
    const float* value      = (const float*)d_in[1];
    const int*   Yinput     = (const int*)d_in[2];
    const int*   frame_lens = (const int*)d_in[3];
    // d_in[4] = max_len scalar; derived from out_size instead
    const float* emb   = (const float*)d_in[5];
    const float* Wq    = (const float*)d_in[6];
    const float* bq    = (const float*)d_in[7];
    const float* Wih1  = (const float*)d_in[8];
    const float* Whh1  = (const float*)d_in[9];
    const float* bih1  = (const float*)d_in[10];
    const float* bhh1  = (const float*)d_in[11];
    const float* Wih2  = (const float*)d_in[12];
    const float* Whh2  = (const float*)d_in[13];
    const float* bih2  = (const float*)d_in[14];
    const float* bhh2  = (const float*)d_in[15];
    const float* Wih3  = (const float*)d_in[16];
    const float* Whh3  = (const float*)d_in[17];
    const float* bih3  = (const float*)d_in[18];
    const float* bhh3  = (const float*)d_in[19];
    const float* Wmlp  = (const float*)d_in[20];
    const float* bmlp  = (const float*)d_in[21];
    const float* bproj = (const float*)d_in[22];
    const float* h00 = (const float*)d_in[23];
    const float* h01 = (const float*)d_in[24];
    const float* h02 = (const float*)d_in[25];
    const float* c00 = (const float*)d_in[26];
    const float* c01 = (const float*)d_in[27];
    const float* c02 = (const float*)d_in[28];

    float* out = (float*)d_out;
    const int ml = out_size / (BATCH * CC);     // 300
    const int ystride = in_sizes[2] / BATCH;    // MAXLEN = 300

    cudaFuncSetAttribute(mega_kernel,
                         cudaFuncAttributeMaxDynamicSharedMemorySize, SMEM_BYTES);

    mega_kernel<<<NBLK, NTHR, SMEM_BYTES>>>(
        key, value, Yinput, frame_lens,
        emb, Wq, bq,
        Wih1, Whh1, bih1, bhh1,
        Wih2, Whh2, bih2, bhh2,
        Wih3, Whh3, bih3, bhh3,
        Wmlp, bmlp, bproj,
        h00, h01, h02, c00, c01, c02,
        out, ml, ystride);
}